// round 11
// baseline (speedup 1.0000x reference)
#include <cuda_runtime.h>
#include <cuda_fp16.h>

#define B_  4
#define C_  192
#define S_  64
#define L_  512
#define SL_ (S_ * L_)

// ---------------------------------------------------------------------------
// Single fused kernel, one block per (b,s):
//   phase 1: q = wq.query + bq ; softmax over L ; kctx = sum_l p[l]*key[:,l];
//            ctx = Wk @ kctx + bk            (ctx stays in smem)
//   phase 2: out = Wo @ (relu(Wv @ X + bv) * ctx) + bo   via fp16 mma.sync
// grid = 256 blocks, 512 threads (16 warps), warp tile m48 x n32, NSUB=128.
// X tile and T tile share one smem buffer (X dead before T is written).
// ---------------------------------------------------------------------------
#define PA 200    // half pitch, weights: word pitch 100 -> bank stride 4 -> conflict-free frags
#define PX 202    // half pitch, X/T tile: word pitch 101 -> conflict-free transposed stores
#define NSUB 128
#define NIT  (L_ / NSUB)   // 4
#define PF   12            // register-prefetched floats per thread (1/4 subtile)

#define SMEM_BYTES ((2 * 192 * PA + NSUB * PX) * 2 + 3 * 192 * 4)  // 207,616

__device__ __forceinline__ void mma16816(float* c, const unsigned* a, const unsigned* bf)
{
    asm volatile(
        "mma.sync.aligned.m16n8k16.row.col.f32.f16.f16.f32 "
        "{%0,%1,%2,%3},{%4,%5,%6,%7},{%8,%9},{%0,%1,%2,%3};\n"
        : "+f"(c[0]), "+f"(c[1]), "+f"(c[2]), "+f"(c[3])
        : "r"(a[0]), "r"(a[1]), "r"(a[2]), "r"(a[3]), "r"(bf[0]), "r"(bf[1]));
}

// D(192 x 128) = A(192 x 192) * B^T. A row-major [m][k] pitch PA,
// B stored [n][k] pitch PX. Per-warp m48 x n32 tile.
__device__ __forceinline__ void gemm192(const __half* __restrict__ Asm,
                                        const __half* __restrict__ Bsm,
                                        int mb, int nb, int g, int tg,
                                        float acc[3][4][4])
{
#pragma unroll
    for (int mi = 0; mi < 3; mi++)
#pragma unroll
        for (int ni = 0; ni < 4; ni++)
#pragma unroll
            for (int r = 0; r < 4; r++) acc[mi][ni][r] = 0.f;

#pragma unroll
    for (int kk = 0; kk < 12; kk++) {
        const int k0 = kk * 16;
        unsigned a[3][4];
#pragma unroll
        for (int mi = 0; mi < 3; mi++) {
            const __half* ap = Asm + (mb + mi * 16 + g) * PA + k0 + 2 * tg;
            a[mi][0] = *(const unsigned*)(ap);
            a[mi][1] = *(const unsigned*)(ap + 8 * PA);
            a[mi][2] = *(const unsigned*)(ap + 8);
            a[mi][3] = *(const unsigned*)(ap + 8 * PA + 8);
        }
        unsigned bf[4][2];
#pragma unroll
        for (int ni = 0; ni < 4; ni++) {
            const __half* bp = Bsm + (nb + ni * 8 + g) * PX + k0 + 2 * tg;
            bf[ni][0] = *(const unsigned*)(bp);
            bf[ni][1] = *(const unsigned*)(bp + 8);
        }
#pragma unroll
        for (int mi = 0; mi < 3; mi++)
#pragma unroll
            for (int ni = 0; ni < 4; ni++)
                mma16816(acc[mi][ni], a[mi], bf[ni]);
    }
}

__global__ __launch_bounds__(512, 1)
void sep_attn_fused_kernel(const float* __restrict__ query,
                           const float* __restrict__ key,
                           const float* __restrict__ value,
                           const float* __restrict__ ipw,
                           const float* __restrict__ ipb,
                           const float* __restrict__ opw,
                           const float* __restrict__ opb,
                           float* __restrict__ out)
{
    extern __shared__ char sm2[];
    __half* A1   = (__half*)sm2;           // Wv  192 x PA
    __half* A2   = A1 + 192 * PA;          // Wo  192 x PA
    __half* Tile = A2 + 192 * PA;          // NSUB x PX ([n][k]); X then T (aliased)
    float* ctx_s = (float*)(Tile + NSUB * PX);
    float* bv_s  = ctx_s + 192;
    float* bo_s  = bv_s + 192;
    // phase-1 scratch aliases the tile buffer (dead until mainloop)
    float* wq_s   = (float*)Tile;          // 192
    float* scores = wq_s + 192;            // 512
    float* kctx   = scores + 512;          // 192
    float* red    = kctx + 192;            // 64

    const int bs   = blockIdx.x;
    const int b    = bs >> 6;
    const int s    = bs & 63;
    const int tid  = threadIdx.x;
    const int lane = tid & 31;
    const int warp = tid >> 5;
    const int g    = lane >> 2;
    const int tg   = lane & 3;
    const int mb   = (warp >> 2) * 48;     // 4 m-groups
    const int nb   = (warp & 3) * 32;      // 4 n-groups over NSUB=128

    const float* vbase = value + (((size_t)b * C_) * S_ + s) * (size_t)L_;
    float*       obase = out   + (((size_t)b * C_) * S_ + s) * (size_t)L_;

    // per-thread slots for X staging: 128 columns x 4 channel-groups
    const int lx = tid & 127;
    const int cb = tid >> 7;               // 0..3; channels c == cb (mod 4)

    // early prefetch of subtile-0's register quarter (hides under phase 1)
    float xr[PF];
#pragma unroll
    for (int m = 0; m < PF; m++)
        xr[m] = vbase[(size_t)(cb + 16 * m) * SL_ + lx];

    // ======================= phase 1: context vector =======================
    if (tid < 192) wq_s[tid] = ipw[tid];
    __syncthreads();

    // q[l], l = tid
    {
        const float* qp = query + (((size_t)b * C_) * S_ + s) * (size_t)L_ + tid;
        float a0 = 0.f, a1 = 0.f;
#pragma unroll 8
        for (int c = 0; c < C_; c += 2) {
            a0 = fmaf(wq_s[c],     qp[(size_t)c * SL_],       a0);
            a1 = fmaf(wq_s[c + 1], qp[(size_t)(c + 1) * SL_], a1);
        }
        float q = a0 + a1 + ipb[0];

        // softmax over 512 threads
        float v = q;
#pragma unroll
        for (int off = 16; off; off >>= 1)
            v = fmaxf(v, __shfl_xor_sync(0xffffffffu, v, off));
        if (lane == 0) red[warp] = v;
        __syncthreads();
        if (warp == 0) {
            float m = (lane < 16) ? red[lane] : -1e30f;
#pragma unroll
            for (int off = 16; off; off >>= 1)
                m = fmaxf(m, __shfl_xor_sync(0xffffffffu, m, off));
            if (lane == 0) red[32] = m;
        }
        __syncthreads();
        float e = __expf(q - red[32]);

        v = e;
#pragma unroll
        for (int off = 16; off; off >>= 1)
            v += __shfl_xor_sync(0xffffffffu, v, off);
        if (lane == 0) red[16 + warp] = v;
        __syncthreads();
        if (warp == 0) {
            float m = (lane < 16) ? red[16 + lane] : 0.f;
#pragma unroll
            for (int off = 16; off; off >>= 1)
                m += __shfl_xor_sync(0xffffffffu, m, off);
            if (lane == 0) red[33] = m;
        }
        __syncthreads();
        scores[tid] = e * (1.f / red[33]);
    }
    __syncthreads();

    // kctx[c] = sum_l scores[l] * key[b,c,s,l]
    for (int c = warp; c < C_; c += 16) {
        const float* kp = key + (((size_t)b * C_ + c) * S_ + s) * (size_t)L_;
        float a = 0.f;
#pragma unroll 4
        for (int l = lane; l < L_; l += 32)
            a = fmaf(scores[l], kp[l], a);
#pragma unroll
        for (int off = 16; off; off >>= 1)
            a += __shfl_xor_sync(0xffffffffu, a, off);
        if (lane == 0) kctx[c] = a;
    }
    __syncthreads();

    // ctx = Wk @ kctx + bk (warp-per-row; Wk is L2-resident across blocks)
#pragma unroll
    for (int j = 0; j < 12; j++) {
        const int o = warp * 12 + j;
        const float* wrow = ipw + (size_t)(1 + o) * C_;
        float a = 0.f;
#pragma unroll
        for (int k = 0; k < 6; k++) {
            int c = lane + k * 32;
            a = fmaf(wrow[c], kctx[c], a);
        }
#pragma unroll
        for (int off = 16; off; off >>= 1)
            a += __shfl_xor_sync(0xffffffffu, a, off);
        if (lane == 0) ctx_s[o] = a + ipb[1 + o];
    }

    // stage weights fp32 -> fp16 smem (L2-hot), biases
    for (int i = tid; i < 192 * 192; i += 512) {
        int o = i / 192, c = i - o * 192;
        A1[o * PA + c] = __float2half(ipw[(1 + C_ + o) * C_ + c]);
        A2[o * PA + c] = __float2half(opw[i]);
    }
    if (tid < 192) {
        bv_s[tid] = ipb[1 + C_ + tid];
        bo_s[tid] = opb[tid];
    }
    __syncthreads();   // phase-1 scratch dead; Tile becomes X/T buffer

    // ======================= phase 2: fused double GEMM ====================
    float acc[3][4][4];

    for (int it = 0; it < NIT; it++) {
        const int n0 = it * NSUB;

        // stage X subtile into Tile (transposed, fp16):
        // prefetched quarter from regs + remaining channels direct from gmem
#pragma unroll
        for (int m = 0; m < PF; m++)
            Tile[lx * PX + cb + 16 * m] = __float2half(xr[m]);
#pragma unroll
        for (int j = 0; j < 48; j++) {
            if ((j & 3) == 0) continue;
            const int c = cb + 4 * j;
            Tile[lx * PX + c] = __float2half(vbase[(size_t)c * SL_ + n0 + lx]);
        }
        __syncthreads();

        // GEMM1: T = relu(Wv @ X + bv) * ctx
        gemm192(A1, Tile, mb, nb, g, tg, acc);
        __syncthreads();   // all of X consumed -> Tile reusable for T

#pragma unroll
        for (int mi = 0; mi < 3; mi++) {
            const int row = mb + mi * 16 + g;
            const float bvl = bv_s[row],     cxl = ctx_s[row];
            const float bvh = bv_s[row + 8], cxh = ctx_s[row + 8];
#pragma unroll
            for (int ni = 0; ni < 4; ni++) {
                const int n = nb + ni * 8 + 2 * tg;
                Tile[n * PX + row]           = __float2half(fmaxf(acc[mi][ni][0] + bvl, 0.f) * cxl);
                Tile[(n + 1) * PX + row]     = __float2half(fmaxf(acc[mi][ni][1] + bvl, 0.f) * cxl);
                Tile[n * PX + row + 8]       = __float2half(fmaxf(acc[mi][ni][2] + bvh, 0.f) * cxh);
                Tile[(n + 1) * PX + row + 8] = __float2half(fmaxf(acc[mi][ni][3] + bvh, 0.f) * cxh);
            }
        }
        __syncthreads();   // T ready

        // prefetch next subtile's register quarter (hides under GEMM2)
        if (it < NIT - 1) {
#pragma unroll
            for (int m = 0; m < PF; m++)
                xr[m] = vbase[(size_t)(cb + 16 * m) * SL_ + n0 + NSUB + lx];
        }

        // GEMM2: out = Wo @ T + bo -> gmem (float2 stores)
        gemm192(A2, Tile, mb, nb, g, tg, acc);
#pragma unroll
        for (int mi = 0; mi < 3; mi++) {
            const int row = mb + mi * 16 + g;
            const float bl = bo_s[row], bh = bo_s[row + 8];
            float* o0 = obase + (size_t)row * SL_ + n0;
#pragma unroll
            for (int ni = 0; ni < 4; ni++) {
                const int n = nb + ni * 8 + 2 * tg;
                float2 lo = make_float2(acc[mi][ni][0] + bl, acc[mi][ni][1] + bl);
                float2 hi = make_float2(acc[mi][ni][2] + bh, acc[mi][ni][3] + bh);
                *(float2*)(o0 + n)                   = lo;
                *(float2*)(o0 + (size_t)8 * SL_ + n) = hi;
            }
        }
        __syncthreads();   // Tile free for next iteration's staging
    }
}

// ---------------------------------------------------------------------------
extern "C" void kernel_launch(void* const* d_in, const int* in_sizes, int n_in,
                              void* d_out, int out_size)
{
    const float* query = (const float*)d_in[0];
    const float* key   = (const float*)d_in[1];
    const float* value = (const float*)d_in[2];
    const float* ipw   = (const float*)d_in[3];
    const float* ipb   = (const float*)d_in[4];
    const float* opw   = (const float*)d_in[5];
    const float* opb   = (const float*)d_in[6];
    float* out = (float*)d_out;

    cudaFuncSetAttribute(sep_attn_fused_kernel,
                         cudaFuncAttributeMaxDynamicSharedMemorySize, SMEM_BYTES);

    sep_attn_fused_kernel<<<B_ * S_, 512, SMEM_BYTES>>>(
        query, key, value, ipw, ipb, opw, opb, out);
}

// round 16
// speedup vs baseline: 1.1539x; 1.1539x over previous
#include <cuda_runtime.h>
#include <cuda_fp16.h>
#include <cstdint>

#define B_  4
#define C_  192
#define S_  64
#define L_  512
#define SL_ (S_ * L_)

// ctx[b][s][c] scratch
__device__ float g_ctx[B_ * S_ * C_];

// ===========================================================================
// Kernel 1 (unchanged, proven): per (b,s) context vector
// ===========================================================================
__global__ __launch_bounds__(512, 2)
void attn_ctx_kernel(const float* __restrict__ query,
                     const float* __restrict__ key,
                     const float* __restrict__ ipw,
                     const float* __restrict__ ipb)
{
    __shared__ float wq_s[192];
    __shared__ float scores[512];
    __shared__ float kctx[192];
    __shared__ float red[64];

    const int bs   = blockIdx.x;
    const int b    = bs >> 6;
    const int s    = bs & 63;
    const int tid  = threadIdx.x;
    const int lane = tid & 31;
    const int warp = tid >> 5;

    if (tid < 192) wq_s[tid] = ipw[tid];
    __syncthreads();

    const float* qp = query + (((size_t)b * C_) * S_ + s) * (size_t)L_ + tid;
    float a0 = 0.f, a1 = 0.f;
#pragma unroll 8
    for (int c = 0; c < C_; c += 2) {
        a0 = fmaf(wq_s[c],     qp[(size_t)c * SL_],       a0);
        a1 = fmaf(wq_s[c + 1], qp[(size_t)(c + 1) * SL_], a1);
    }
    float q = a0 + a1 + ipb[0];

    float v = q;
#pragma unroll
    for (int off = 16; off; off >>= 1)
        v = fmaxf(v, __shfl_xor_sync(0xffffffffu, v, off));
    if (lane == 0) red[warp] = v;
    __syncthreads();
    if (warp == 0) {
        float m = (lane < 16) ? red[lane] : -1e30f;
#pragma unroll
        for (int off = 16; off; off >>= 1)
            m = fmaxf(m, __shfl_xor_sync(0xffffffffu, m, off));
        if (lane == 0) red[32] = m;
    }
    __syncthreads();
    float e = __expf(q - red[32]);

    v = e;
#pragma unroll
    for (int off = 16; off; off >>= 1)
        v += __shfl_xor_sync(0xffffffffu, v, off);
    if (lane == 0) red[16 + warp] = v;
    __syncthreads();
    if (warp == 0) {
        float m = (lane < 16) ? red[16 + lane] : 0.f;
#pragma unroll
        for (int off = 16; off; off >>= 1)
            m += __shfl_xor_sync(0xffffffffu, m, off);
        if (lane == 0) red[33] = m;
    }
    __syncthreads();
    scores[tid] = e * (1.f / red[33]);
    __syncthreads();

    for (int c = warp; c < C_; c += 16) {
        const float* kp = key + (((size_t)b * C_ + c) * S_ + s) * (size_t)L_;
        float a = 0.f;
#pragma unroll 4
        for (int l = lane; l < L_; l += 32)
            a = fmaf(scores[l], kp[l], a);
#pragma unroll
        for (int off = 16; off; off >>= 1)
            a += __shfl_xor_sync(0xffffffffu, a, off);
        if (lane == 0) kctx[c] = a;
    }
    __syncthreads();

#pragma unroll
    for (int j = 0; j < 12; j++) {
        const int o = warp * 12 + j;
        const float* wrow = ipw + (size_t)(1 + o) * C_;
        float a = 0.f;
#pragma unroll
        for (int k = 0; k < 6; k++) {
            int c = lane + k * 32;
            a = fmaf(wrow[c], kctx[c], a);
        }
#pragma unroll
        for (int off = 16; off; off >>= 1)
            a += __shfl_xor_sync(0xffffffffu, a, off);
        if (lane == 0) g_ctx[(size_t)bs * C_ + o] = a + ipb[1 + o];
    }
}

// ===========================================================================
// Kernel 2: per (b,s): out = Wo @ (relu(Wv @ X + bv) * ctx) + bo
// fp16 mma.sync m16n8k16 + ldmatrix A-fragments. 512 threads (16 warps),
// warp tile m48 x n32 over NSUB=128; X/T share one smem tile.
// ===========================================================================
#define PA 200   // half pitch, weights: 400B rows (16B-aligned for ldmatrix, LDSM conflict-free)
#define PX 202   // half pitch, X/T tile: odd word pitch -> conflict-free transposed stores
#define NSUB 128
#define NIT  (L_ / NSUB)   // 4

#define K2_SMEM ((2 * 192 * PA + NSUB * PX) * 2 + 3 * 192 * 4)  // 207,616

__device__ __forceinline__ uint32_t smem_u32(const void* p) {
    uint32_t a;
    asm("{ .reg .u64 t; cvta.to.shared.u64 t, %1; cvt.u32.u64 %0, t; }"
        : "=r"(a) : "l"(p));
    return a;
}

__device__ __forceinline__ void mma16816(float* c, const unsigned* a, const unsigned* bf)
{
    asm volatile(
        "mma.sync.aligned.m16n8k16.row.col.f32.f16.f16.f32 "
        "{%0,%1,%2,%3},{%4,%5,%6,%7},{%8,%9},{%0,%1,%2,%3};\n"
        : "+f"(c[0]), "+f"(c[1]), "+f"(c[2]), "+f"(c[3])
        : "r"(a[0]), "r"(a[1]), "r"(a[2]), "r"(a[3]), "r"(bf[0]), "r"(bf[1]));
}

__device__ __forceinline__ void ldsm4(unsigned* r, uint32_t addr)
{
    asm volatile("ldmatrix.sync.aligned.m8n8.x4.shared.b16 {%0,%1,%2,%3}, [%4];"
                 : "=r"(r[0]), "=r"(r[1]), "=r"(r[2]), "=r"(r[3]) : "r"(addr));
}

// D(192 x 128) = A(192 x 192) @ B^T. A row-major [m][k] pitch PA (ldmatrix),
// B stored [n][k] pitch PX (scalar LDS). Per-warp m48 x n32 tile.
__device__ __forceinline__ void gemm192(uint32_t Au, const __half* __restrict__ Bsm,
                                        int mb, int nb, int lane, float acc[3][4][4])
{
#pragma unroll
    for (int mi = 0; mi < 3; mi++)
#pragma unroll
        for (int ni = 0; ni < 4; ni++)
#pragma unroll
            for (int r = 0; r < 4; r++) acc[mi][ni][r] = 0.f;

    const int g  = lane >> 2;
    const int tg = lane & 3;
    // ldmatrix lane-address mapping: q0:(m0,k0) q1:(m8,k0) q2:(m0,k8) q3:(m8,k8)
    const int q  = lane >> 3, lr = lane & 7;
    const uint32_t abase = Au + (uint32_t)((mb + ((q & 1) << 3) + lr) * PA
                                           + ((q >> 1) << 3)) * 2u;

#pragma unroll
    for (int kk = 0; kk < 12; kk++) {
        const int k0 = kk * 16;
        unsigned a[3][4];
#pragma unroll
        for (int mi = 0; mi < 3; mi++)
            ldsm4(a[mi], abase + (uint32_t)(mi * 16 * PA + k0) * 2u);

        unsigned bf[4][2];
#pragma unroll
        for (int ni = 0; ni < 4; ni++) {
            const __half* bp = Bsm + (nb + ni * 8 + g) * PX + k0 + 2 * tg;
            bf[ni][0] = *(const unsigned*)(bp);
            bf[ni][1] = *(const unsigned*)(bp + 8);
        }
#pragma unroll
        for (int mi = 0; mi < 3; mi++)
#pragma unroll
            for (int ni = 0; ni < 4; ni++)
                mma16816(acc[mi][ni], a[mi], bf[ni]);
    }
}

__global__ __launch_bounds__(512, 1)
void fused_vproj_out_kernel(const float* __restrict__ value,
                            const float* __restrict__ ipw,
                            const float* __restrict__ ipb,
                            const float* __restrict__ opw,
                            const float* __restrict__ opb,
                            float* __restrict__ out)
{
    extern __shared__ char sm2[];
    __half* A1   = (__half*)sm2;           // Wv  192 x PA
    __half* A2   = A1 + 192 * PA;          // Wo  192 x PA
    __half* Tile = A2 + 192 * PA;          // NSUB x PX ([n][k]); X then T (aliased)
    float* ctx_s = (float*)(Tile + NSUB * PX);
    float* bv_s  = ctx_s + 192;
    float* bo_s  = bv_s + 192;

    const int bs   = blockIdx.x;
    const int b    = bs >> 6;
    const int s    = bs & 63;
    const int tid  = threadIdx.x;
    const int lane = tid & 31;
    const int warp = tid >> 5;
    const int g    = lane >> 2;
    const int tg   = lane & 3;
    const int mb   = (warp >> 2) * 48;     // 4 m-groups
    const int nb   = (warp & 3) * 32;      // 4 n-groups over NSUB=128

    const uint32_t A1u = smem_u32(A1);
    const uint32_t A2u = smem_u32(A2);

    const float* vbase = value + (((size_t)b * C_) * S_ + s) * (size_t)L_;
    float*       obase = out   + (((size_t)b * C_) * S_ + s) * (size_t)L_;

    // staging map: row lx (0..127), channel pairs c = 2*cg + 8*j, j = 0..23
    const int lx = tid & 127;
    const int cg = tid >> 7;

    // prefetch half of subtile 0 (hides under weight staging)
    float xr[24];
#pragma unroll
    for (int j = 0; j < 12; j++) {
        const int c = 2 * cg + 8 * j;
        xr[2 * j]     = vbase[(size_t)c * SL_ + lx];
        xr[2 * j + 1] = vbase[(size_t)(c + 1) * SL_ + lx];
    }

    // stage weights fp32 -> fp16 smem (L2-hot), ctx + biases
    for (int i = tid; i < 192 * 192; i += 512) {
        int o = i / 192, c = i - o * 192;
        A1[o * PA + c] = __float2half(ipw[(size_t)(1 + C_ + o) * C_ + c]);
        A2[o * PA + c] = __float2half(opw[i]);
    }
    if (tid < 192) {
        ctx_s[tid] = g_ctx[(size_t)bs * C_ + tid];
        bv_s[tid]  = ipb[1 + C_ + tid];
        bo_s[tid]  = opb[tid];
    }
    __syncthreads();

    float acc[3][4][4];

    for (int it = 0; it < NIT; it++) {
        const int n0 = it * NSUB;

        // ---- stage X subtile [l][c] fp16: batch-load direct half, then store all ----
        {
            float xd[24];
#pragma unroll
            for (int j = 12; j < 24; j++) {
                const int c = 2 * cg + 8 * j;
                xd[2 * (j - 12)]     = vbase[(size_t)c * SL_ + n0 + lx];
                xd[2 * (j - 12) + 1] = vbase[(size_t)(c + 1) * SL_ + n0 + lx];
            }
#pragma unroll
            for (int j = 0; j < 12; j++) {
                const int c = 2 * cg + 8 * j;
                *(__half2*)(Tile + lx * PX + c) = __floats2half2_rn(xr[2 * j], xr[2 * j + 1]);
            }
#pragma unroll
            for (int j = 12; j < 24; j++) {
                const int c = 2 * cg + 8 * j;
                *(__half2*)(Tile + lx * PX + c) =
                    __floats2half2_rn(xd[2 * (j - 12)], xd[2 * (j - 12) + 1]);
            }
        }
        __syncthreads();

        // ---- GEMM1: D = Wv @ X ----
        gemm192(A1u, Tile, mb, nb, lane, acc);
        __syncthreads();   // all of X consumed -> Tile reusable for T

        // ---- epilogue 1: T = relu(D + bv) * ctx -> Tile (transposed, fp16) ----
#pragma unroll
        for (int mi = 0; mi < 3; mi++) {
            const int row = mb + mi * 16 + g;
            const float bvl = bv_s[row],     cxl = ctx_s[row];
            const float bvh = bv_s[row + 8], cxh = ctx_s[row + 8];
#pragma unroll
            for (int ni = 0; ni < 4; ni++) {
                const int n = nb + ni * 8 + 2 * tg;
                Tile[n * PX + row]           = __float2half(fmaxf(acc[mi][ni][0] + bvl, 0.f) * cxl);
                Tile[(n + 1) * PX + row]     = __float2half(fmaxf(acc[mi][ni][1] + bvl, 0.f) * cxl);
                Tile[n * PX + row + 8]       = __float2half(fmaxf(acc[mi][ni][2] + bvh, 0.f) * cxh);
                Tile[(n + 1) * PX + row + 8] = __float2half(fmaxf(acc[mi][ni][3] + bvh, 0.f) * cxh);
            }
        }
        __syncthreads();   // T ready

        // prefetch next subtile's register half (hides under GEMM2)
        if (it < NIT - 1) {
            const int n1 = n0 + NSUB;
#pragma unroll
            for (int j = 0; j < 12; j++) {
                const int c = 2 * cg + 8 * j;
                xr[2 * j]     = vbase[(size_t)c * SL_ + n1 + lx];
                xr[2 * j + 1] = vbase[(size_t)(c + 1) * SL_ + n1 + lx];
            }
        }

        // ---- GEMM2: out = Wo @ T + bo -> gmem ----
        gemm192(A2u, Tile, mb, nb, lane, acc);
#pragma unroll
        for (int mi = 0; mi < 3; mi++) {
            const int row = mb + mi * 16 + g;
            const float bl = bo_s[row], bh = bo_s[row + 8];
            float* o0 = obase + (size_t)row * SL_ + n0;
#pragma unroll
            for (int ni = 0; ni < 4; ni++) {
                const int n = nb + ni * 8 + 2 * tg;
                float2 lo = make_float2(acc[mi][ni][0] + bl, acc[mi][ni][1] + bl);
                float2 hi = make_float2(acc[mi][ni][2] + bh, acc[mi][ni][3] + bh);
                *(float2*)(o0 + n)                   = lo;
                *(float2*)(o0 + (size_t)8 * SL_ + n) = hi;
            }
        }
        __syncthreads();   // Tile free for next iteration's staging
    }
}

// ---------------------------------------------------------------------------
extern "C" void kernel_launch(void* const* d_in, const int* in_sizes, int n_in,
                              void* d_out, int out_size)
{
    const float* query = (const float*)d_in[0];
    const float* key   = (const float*)d_in[1];
    const float* value = (const float*)d_in[2];
    const float* ipw   = (const float*)d_in[3];
    const float* ipb   = (const float*)d_in[4];
    const float* opw   = (const float*)d_in[5];
    const float* opb   = (const float*)d_in[6];
    float* out = (float*)d_out;

    cudaFuncSetAttribute(fused_vproj_out_kernel,
                         cudaFuncAttributeMaxDynamicSharedMemorySize, K2_SMEM);

    attn_ctx_kernel<<<B_ * S_, 512>>>(query, key, ipw, ipb);
    fused_vproj_out_kernel<<<B_ * S_, 512, K2_SMEM>>>(value, ipw, ipb, opw, opb, out);
}